// round 16
// baseline (speedup 1.0000x reference)
#include <cuda_runtime.h>
#include <cuda_fp16.h>

// Problem constants (fixed shapes per reference)
#define N_NODES  100000
#define E_EDGES  1000000
#define N_REL    16
#define N_BASES  8
#define CHUNK    2048
#define NCHUNKS  489
#define NCH_A    245         // sort launch A chunks
#define NC       9           // K3 segments per relation: 9*16 = 144 CTAs (1/SM)
#define TILE_M   128
#define RELU_B   6250        // relu blocks: N_NODES*64/4/256
#define THREADS  512         // 8 MMA warps + 8 epilogue warps

// SMEM layout (bytes). A rows 144 B (conflict-free ldmatrix);
// D staging 288 B stride (R13/R15-proven conflict-free), double-buffered.
#define A_STRIDE 144
#define D_STRIDE 288
#define ABUF_SZ  18432       // one A buffer (128 x 144 fp16 rows)
#define DBUF_SZ  36864       // one D buffer (128 x 288)
#define SM_A     0           // 2 x 18432
#define SM_BHI   36864       // B[n][k] fp16 hi: 64 x 144
#define SM_BLO   46080       // B[n][k] fp16 lo
#define SM_D     55296       // 2 x 36864
#define SM_DST   129024      // 2 x 512 (A-side dst, written by gather)
#define SM_DDST  130048      // 2 x 512 (D-side dst, read by epilogue)
#define SM_BYTES 131072

#define BAR_SYNC(id, cnt)   asm volatile("bar.sync %0, %1;"   :: "r"(id), "r"(cnt) : "memory")
#define BAR_ARRIVE(id, cnt) asm volatile("bar.arrive %0, %1;" :: "r"(id), "r"(cnt) : "memory")

// ---------------------------------------------------------------------------
// Device scratch (static only — no cudaMalloc allowed)
// ---------------------------------------------------------------------------
__device__ float d_W[N_REL * 64 * 64];   // W[r][k][o] at r*4096 + k*64 + o
__device__ int   d_cnt[N_REL];           // zero-init; reset each replay
__device__ int   d_done;                 // zero-init; reset each replay
__device__ int   d_off[N_REL + 1];
__device__ int   d_cur[N_REL];
__device__ int2  d_se[E_EDGES];          // edges sorted by relation {src,dst}
// Precomputed fp16 copy of h: row n = 64 fp16 = 128 B (line-aligned).
__device__ __align__(128) uint4 d_hf[N_NODES * 8];

// ---------------------------------------------------------------------------
__device__ __forceinline__ unsigned smem_u32(const void* p) {
    unsigned r;
    asm("{ .reg .u64 t; cvta.to.shared.u64 t, %1; cvt.u32.u64 %0, t; }"
        : "=r"(r) : "l"(p));
    return r;
}
__device__ __forceinline__ unsigned pk2h(__half a, __half b) {
    unsigned short ua = *(unsigned short*)&a, ub = *(unsigned short*)&b;
    return (unsigned)ua | ((unsigned)ub << 16);
}
__device__ __forceinline__ void ldsm_x4(unsigned a[4], unsigned addr) {
    asm volatile("ldmatrix.sync.aligned.m8n8.x4.shared.b16 {%0,%1,%2,%3}, [%4];"
                 : "=r"(a[0]), "=r"(a[1]), "=r"(a[2]), "=r"(a[3]) : "r"(addr));
}
__device__ __forceinline__ void mma_f16(float c[4], const unsigned a[4],
                                        unsigned b0, unsigned b1) {
    asm volatile(
        "mma.sync.aligned.m16n8k16.row.col.f32.f16.f16.f32 "
        "{%0,%1,%2,%3}, {%4,%5,%6,%7}, {%8,%9}, {%0,%1,%2,%3};"
        : "+f"(c[0]), "+f"(c[1]), "+f"(c[2]), "+f"(c[3])
        : "r"(a[0]), "r"(a[1]), "r"(a[2]), "r"(a[3]), "r"(b0), "r"(b1));
}

// ---------------------------------------------------------------------------
// L0: fused kernel — three independent block families (proven R11-R15):
//   [0,256):            W basis combination (reference reshape quirk)
//   [256,256+NCHUNKS):  rel histogram; last CTA scans -> d_off/d_cur + resets
//   [745, +RELU_B):     relu(h)->out, zero h2, fp16 copy of h
// ---------------------------------------------------------------------------
__global__ void l0_fused_kernel(const float* __restrict__ weight,
                                const float* __restrict__ w_comp,
                                const int* __restrict__ rel,
                                const float4* __restrict__ h,
                                float4* __restrict__ out) {
    const int tid = threadIdx.x;
    if (blockIdx.x < 256) {
        int idx = blockIdx.x * 256 + tid;
        int im = idx >> 10;
        int rm = (idx >> 6) & 15;
        int om = idx & 63;
        float s = 0.f;
#pragma unroll
        for (int b = 0; b < N_BASES; b++)
            s += w_comp[rm * N_BASES + b] * weight[im * 512 + b * 64 + om];
        d_W[idx] = s;
        return;
    }
    if (blockIdx.x >= 256 + NCHUNKS) {
        int i = (blockIdx.x - (256 + NCHUNKS)) * 256 + tid;
        const int n4 = N_NODES * 64 / 4;
        if (i >= n4) return;
        float4 v = h[i];
        unsigned p0 = pk2h(__float2half_rn(v.x), __float2half_rn(v.y));
        unsigned p1 = pk2h(__float2half_rn(v.z), __float2half_rn(v.w));
        ((uint2*)d_hf)[i] = make_uint2(p0, p1);
        v.x = fmaxf(v.x, 0.f);
        v.y = fmaxf(v.y, 0.f);
        v.z = fmaxf(v.z, 0.f);
        v.w = fmaxf(v.w, 0.f);
        out[i] = v;
        out[n4 + i] = make_float4(0.f, 0.f, 0.f, 0.f);
        return;
    }
    __shared__ int hc[N_REL];
    __shared__ int is_last;
    if (tid < N_REL) hc[tid] = 0;
    if (tid == 0) is_last = 0;
    __syncthreads();
    int base = (blockIdx.x - 256) * CHUNK;
#pragma unroll 2
    for (int j = tid; j < CHUNK; j += 256) {
        int e = base + j;
        if (e < E_EDGES) atomicAdd(&hc[rel[e]], 1);
    }
    __syncthreads();
    if (tid < N_REL) atomicAdd(&d_cnt[tid], hc[tid]);
    __threadfence();
    if (tid == 0) {
        int prev = atomicAdd(&d_done, 1);
        if (prev == NCHUNKS - 1) is_last = 1;
    }
    __syncthreads();
    if (is_last && tid < 32) {
        int c = (tid < N_REL) ? atomicAdd(&d_cnt[tid], 0) : 0;
        int v = c;
#pragma unroll
        for (int d = 1; d < N_REL; d <<= 1) {
            int u = __shfl_up_sync(0xffffffffu, v, d);
            if (tid >= d) v += u;
        }
        if (tid < N_REL) {
            int excl = v - c;
            d_off[tid] = excl;
            d_cur[tid] = excl;
            d_cnt[tid] = 0;
        }
        if (tid == 0) {
            d_off[N_REL] = E_EDGES;
            d_done = 0;
        }
    }
}

// ---------------------------------------------------------------------------
// L1a/L1b: counting-sort scatter by relation (rel chunk staged in SMEM).
// ---------------------------------------------------------------------------
__global__ void sort_kernel(const int* __restrict__ src,
                            const int* __restrict__ dst,
                            const int* __restrict__ rel,
                            int chunk_base) {
    __shared__ int hc[N_REL];
    __shared__ int rl[CHUNK];
    int tid = threadIdx.x;
    if (tid < N_REL) hc[tid] = 0;
    __syncthreads();
    int base = (chunk_base + blockIdx.x) * CHUNK;
#pragma unroll 4
    for (int j = tid; j < CHUNK; j += 256) {
        int e = base + j;
        int rv = (e < E_EDGES) ? __ldg(&rel[e]) : -1;
        rl[j] = rv;
        if (rv >= 0) atomicAdd(&hc[rv], 1);
    }
    __syncthreads();
    if (tid < N_REL) hc[tid] = atomicAdd(&d_cur[tid], hc[tid]);
    __syncthreads();
#pragma unroll 2
    for (int j = tid; j < CHUNK; j += 256) {
        int rv = rl[j];
        if (rv >= 0) {
            int e = base + j;
            int p = atomicAdd(&hc[rv], 1);
            d_se[p] = make_int2(src[e], dst[e]);
        }
    }
}

// ---------------------------------------------------------------------------
// L3: warp-specialized fp16 2-product HMMA GEMM + scatter.
//   Warps 0-7 (producers): cp.async gather, HMMA (W_hi + W_lo products),
//     stage D into double-buffered SMEM region.
//   Warps 8-15 (consumers): read D rows, row-coalesced red.global.add.v4.
//   Handshake: named barriers d_ready (2,3) / epi_free (4,5), count 512,
//   bar.arrive / bar.sync split so both sides run concurrently.
// ---------------------------------------------------------------------------
__global__ void __launch_bounds__(THREADS, 1)
mma_scatter_kernel(float* __restrict__ h2) {
    extern __shared__ __align__(16) char dsm[];
    const unsigned sb = smem_u32(dsm);

    const int r = blockIdx.y;
    const int c = blockIdx.x;
    const int start = d_off[r];
    const int cnt   = d_off[r + 1] - start;
    const int seg   = (cnt + NC - 1) / NC;
    const int s0    = start + c * seg;
    const int s1    = min(start + cnt, s0 + seg);

    const int tid  = threadIdx.x;
    const int wid  = tid >> 5;
    const int lane = tid & 31;
    const int g    = lane >> 2;      // fragment row group
    const int t    = lane & 3;       // fragment col group

    // ---- stage B = W[r] as [n][k] fp16 hi/lo, padded rows (all threads) ----
    for (int idx = tid; idx < 2048; idx += THREADS) {
        int k2 = idx >> 6;
        int o  = idx & 63;
        float x0 = d_W[r * 4096 + (2 * k2) * 64 + o];
        float x1 = d_W[r * 4096 + (2 * k2 + 1) * 64 + o];
        __half h0 = __float2half_rn(x0), h1 = __float2half_rn(x1);
        __half l0 = __float2half_rn(x0 - __half2float(h0));
        __half l1 = __float2half_rn(x1 - __half2float(h1));
        *(unsigned*)(dsm + SM_BHI + o * A_STRIDE + k2 * 4) = pk2h(h0, h1);
        *(unsigned*)(dsm + SM_BLO + o * A_STRIDE + k2 * 4) = pk2h(l0, l1);
    }
    __syncthreads();
    if (s0 >= s1) return;                 // uniform per CTA

    const int nt = (s1 - s0 + TILE_M - 1) / TILE_M;

    if (wid < 8) {
        // =================== PRODUCER: gather + MMA + stage D ===============
        const int rowblk = (wid & 3) * 32;
        const int nhalf  = wid >> 2;
        const unsigned a_lane_off =
            (unsigned)((lane & 15) * A_STRIDE + ((lane >> 4) & 1) * 16);
        const unsigned b4_lane_off =
            (unsigned)(((lane >> 4) & 1) * 8 * A_STRIDE + (lane & 7) * A_STRIDE
                       + ((lane >> 3) & 1) * 16);

        // hoist B fragments into registers (CTA-constant W)
        unsigned bh[4][2][4], bl[4][2][4];
#pragma unroll
        for (int kb = 0; kb < 4; kb++)
#pragma unroll
            for (int p = 0; p < 2; p++) {
                unsigned baddr = sb
                    + (unsigned)((nhalf * 32 + p * 16) * A_STRIDE + kb * 32)
                    + b4_lane_off;
                ldsm_x4(bh[kb][p], baddr + SM_BHI);
                ldsm_x4(bl[kb][p], baddr + SM_BLO);
            }

        const int gseg   = tid & 7;       // 16 B segment within a 128 B row
        const int grow_b = tid >> 3;      // row base (0..31), +32 per pass

        int2 sd_pf[4];
#pragma unroll
        for (int p = 0; p < 4; p++) {
            int eidx = min(s0 + p * 32 + grow_b, s1 - 1);
            sd_pf[p] = __ldg(&d_se[eidx]);
        }

        auto issue_gather = [&](const int2 sd[4], int buf) {
            const unsigned abase = sb + SM_A + (unsigned)(buf * ABUF_SZ);
#pragma unroll
            for (int p = 0; p < 4; p++) {
                int grow = p * 32 + grow_b;
                if (gseg == 0)
                    *(int*)(dsm + SM_DST + buf * 512 + grow * 4) = sd[p].y;
                unsigned da = abase + (unsigned)(grow * A_STRIDE + gseg * 16);
                const uint4* gh = d_hf + (long)sd[p].x * 8 + gseg;
                asm volatile("cp.async.ca.shared.global [%0], [%1], 16;"
                             :: "r"(da), "l"(gh) : "memory");
            }
            asm volatile("cp.async.commit_group;" ::: "memory");
        };

        issue_gather(sd_pf, 0);
#pragma unroll
        for (int p = 0; p < 4; p++) {
            int eidx = min(s0 + TILE_M + p * 32 + grow_b, s1 - 1);
            sd_pf[p] = __ldg(&d_se[eidx]);
        }

        for (int it = 0; it < nt; it++) {
            const int tb  = s0 + it * TILE_M;
            const int cur = it & 1;

            asm volatile("cp.async.wait_group 0;" ::: "memory");
            BAR_SYNC(1, 256);             // A(cur) visible; prior reads done

            if (it + 1 < nt) issue_gather(sd_pf, cur ^ 1);
#pragma unroll
            for (int p = 0; p < 4; p++) {
                int eidx = min(tb + 2 * TILE_M + p * 32 + grow_b, s1 - 1);
                sd_pf[p] = __ldg(&d_se[eidx]);
            }

            // ---- MMA on A buffer `cur` ----
            const unsigned abuf = sb + SM_A + (unsigned)(cur * ABUF_SZ);
            float cf[2][4][4];
#pragma unroll
            for (int m = 0; m < 2; m++)
#pragma unroll
                for (int nb = 0; nb < 4; nb++)
#pragma unroll
                    for (int q = 0; q < 4; q++) cf[m][nb][q] = 0.f;

#pragma unroll
            for (int kb = 0; kb < 4; kb++) {
#pragma unroll
                for (int m = 0; m < 2; m++) {
                    unsigned ah[4];
                    unsigned aaddr = abuf
                        + (unsigned)((rowblk + m * 16) * A_STRIDE + kb * 32)
                        + a_lane_off;
                    ldsm_x4(ah, aaddr);
#pragma unroll
                    for (int nb = 0; nb < 4; nb++) {
                        unsigned b0h = bh[kb][nb >> 1][(nb & 1) * 2];
                        unsigned b1h = bh[kb][nb >> 1][(nb & 1) * 2 + 1];
                        unsigned b0l = bl[kb][nb >> 1][(nb & 1) * 2];
                        unsigned b1l = bl[kb][nb >> 1][(nb & 1) * 2 + 1];
                        mma_f16(cf[m][nb], ah, b0h, b1h);
                        mma_f16(cf[m][nb], ah, b0l, b1l);
                    }
                }
            }

            // ---- wait for epilogue to free D[cur], then stage ----
            BAR_SYNC(4 + cur, THREADS);   // epi_free[cur]
            {
                char* dbase = dsm + SM_D + cur * DBUF_SZ;
#pragma unroll
                for (int m = 0; m < 2; m++) {
                    int row0 = rowblk + m * 16 + g;
#pragma unroll
                    for (int nb = 0; nb < 4; nb++) {
                        int col = nhalf * 32 + nb * 8 + 2 * t;
                        *(float2*)(dbase + row0 * D_STRIDE + col * 4) =
                            make_float2(cf[m][nb][0], cf[m][nb][1]);
                        *(float2*)(dbase + (row0 + 8) * D_STRIDE + col * 4) =
                            make_float2(cf[m][nb][2], cf[m][nb][3]);
                    }
                }
                // copy dst indices A-side -> D-side (gather(it+2) may rewrite)
                if (tid < 128)
                    *(int*)(dsm + SM_DDST + cur * 512 + tid * 4) =
                        *(const int*)(dsm + SM_DST + cur * 512 + tid * 4);
            }
            BAR_ARRIVE(2 + cur, THREADS); // d_ready[cur]
        }
    } else {
        // =================== CONSUMER: scatter D -> h2 ======================
        const int ewid  = wid - 8;
        const int seg16 = lane & 15;
        const int rhalf = lane >> 4;

        BAR_ARRIVE(4, THREADS);           // pre-arm epi_free[0]
        BAR_ARRIVE(5, THREADS);           // pre-arm epi_free[1]

        for (int it = 0; it < nt; it++) {
            const int tb  = s0 + it * TILE_M;
            const int mt  = min(TILE_M, s1 - tb);
            const int cur = it & 1;

            BAR_SYNC(2 + cur, THREADS);   // d_ready[cur]
            const char* dbase = dsm + SM_D + cur * DBUF_SZ;
#pragma unroll
            for (int i = 0; i < 8; i++) {
                int row = ewid * 16 + 2 * i + rhalf;
                int dn  = *(const int*)(dsm + SM_DDST + cur * 512 + row * 4);
                float4 v = *(const float4*)(dbase + row * D_STRIDE + seg16 * 16);
                if (row < mt) {
                    float* p = h2 + (long)dn * 64 + seg16 * 4;
                    asm volatile("red.global.add.v4.f32 [%0], {%1,%2,%3,%4};"
                                 :: "l"(p), "f"(v.x), "f"(v.y), "f"(v.z), "f"(v.w)
                                 : "memory");
                }
            }
            BAR_ARRIVE(4 + cur, THREADS); // epi_free[cur]
        }
    }
}

// ---------------------------------------------------------------------------
extern "C" void kernel_launch(void* const* d_in, const int* in_sizes, int n_in,
                              void* d_out, int out_size) {
    const float* h      = (const float*)d_in[0];
    const float* weight = (const float*)d_in[1];
    const float* w_comp = (const float*)d_in[2];
    const int*   src    = (const int*)d_in[3];
    const int*   dst    = (const int*)d_in[4];
    const int*   rel    = (const int*)d_in[5];
    float* out = (float*)d_out;          // [h_new (N*64) | h2 (N*64)]
    float* h2  = out + N_NODES * 64;

    static int smem_set = 0;
    if (!smem_set) {
        cudaFuncSetAttribute(mma_scatter_kernel,
                             cudaFuncAttributeMaxDynamicSharedMemorySize, SM_BYTES);
        smem_set = 1;
    }

    // Launch 0: W + histogram/scan + relu/fp16/zero (fused)
    l0_fused_kernel<<<256 + NCHUNKS + RELU_B, 256>>>(weight, w_comp, rel,
                                                     (const float4*)h,
                                                     (float4*)out);
    // Launches 1+2: counting sort (split so K3 sits at capture slot 3)
    sort_kernel<<<NCH_A, 256>>>(src, dst, rel, 0);
    sort_kernel<<<NCHUNKS - NCH_A, 256>>>(src, dst, rel, NCH_A);
    // Launch 3: warp-specialized fp16 HMMA edge GEMM + scatter
    dim3 grid(NC, N_REL);
    mma_scatter_kernel<<<grid, THREADS, SM_BYTES>>>(h2);
}

// round 17
// speedup vs baseline: 1.0695x; 1.0695x over previous
#include <cuda_runtime.h>
#include <cuda_fp16.h>

// Problem constants (fixed shapes per reference)
#define N_NODES  100000
#define E_EDGES  1000000
#define N_REL    16
#define N_BASES  8
#define CHUNK    2048
#define NCHUNKS  489
#define NCH_A    245         // sort chunks in launch 1 (rest in launch 2)
#define NC       18          // K3 segments per relation: 18*16 = 288 CTAs
#define TILE_M   128
#define RELU_B   6250        // relu blocks: N_NODES*64/4/256
#define BUCKET   70016       // static per-relation edge bucket (>30 sigma margin)

// SMEM layout (bytes). A rows padded to 144 B (conflict-free ldmatrix).
// D staging: dedicated region, 288 B stride (R13/R15-proven conflict-free).
#define A_STRIDE 144
#define D_STRIDE 288
#define ABUF_SZ  18432       // per A buffer (fp16 rows only)
#define SM_BHI   36864       // B[n][k] fp16 hi: 64 x 144
#define SM_BLO   46080       // B[n][k] fp16 lo
#define SM_D     55296       // D staging: 128 x 288
#define SM_DST   92160       // 2 x 128 ints
#define SM_BYTES 93184

// ---------------------------------------------------------------------------
// Device scratch (static only — no cudaMalloc allowed)
// ---------------------------------------------------------------------------
__device__ float d_W[N_REL * 64 * 64];   // W[r][k][o] at r*4096 + k*64 + o
__device__ int   d_cur[N_REL];           // per-relation fill count (zero-init;
                                         // reset by L0 each replay)
__device__ int2  d_se[N_REL * BUCKET];   // bucketed edges {src, dst}
// Precomputed fp16 copy of h: row n = 64 fp16 = 128 B (line-aligned).
__device__ __align__(128) uint4 d_hf[N_NODES * 8];

// ---------------------------------------------------------------------------
__device__ __forceinline__ unsigned smem_u32(const void* p) {
    unsigned r;
    asm("{ .reg .u64 t; cvta.to.shared.u64 t, %1; cvt.u32.u64 %0, t; }"
        : "=r"(r) : "l"(p));
    return r;
}
__device__ __forceinline__ unsigned pk2h(__half a, __half b) {
    unsigned short ua = *(unsigned short*)&a, ub = *(unsigned short*)&b;
    return (unsigned)ua | ((unsigned)ub << 16);
}
__device__ __forceinline__ void ldsm_x4(unsigned a[4], unsigned addr) {
    asm volatile("ldmatrix.sync.aligned.m8n8.x4.shared.b16 {%0,%1,%2,%3}, [%4];"
                 : "=r"(a[0]), "=r"(a[1]), "=r"(a[2]), "=r"(a[3]) : "r"(addr));
}
__device__ __forceinline__ void mma_f16(float c[4], const unsigned a[4],
                                        unsigned b0, unsigned b1) {
    asm volatile(
        "mma.sync.aligned.m16n8k16.row.col.f32.f16.f16.f32 "
        "{%0,%1,%2,%3}, {%4,%5,%6,%7}, {%8,%9}, {%0,%1,%2,%3};"
        : "+f"(c[0]), "+f"(c[1]), "+f"(c[2]), "+f"(c[3])
        : "r"(a[0]), "r"(a[1]), "r"(a[2]), "r"(a[3]), "r"(b0), "r"(b1));
}

// ---------------------------------------------------------------------------
// L0: W basis combination (256 blocks, reference reshape quirk) + 1 block
//     that resets d_cur for this replay's sort.
// ---------------------------------------------------------------------------
__global__ void l0_kernel(const float* __restrict__ weight,
                          const float* __restrict__ w_comp) {
    const int tid = threadIdx.x;
    if (blockIdx.x == 256) {
        if (tid < N_REL) d_cur[tid] = 0;
        return;
    }
    int idx = blockIdx.x * 256 + tid;
    int im = idx >> 10;
    int rm = (idx >> 6) & 15;
    int om = idx & 63;
    float s = 0.f;
#pragma unroll
    for (int b = 0; b < N_BASES; b++)
        s += w_comp[rm * N_BASES + b] * weight[im * 512 + b * 64 + om];
    d_W[idx] = s;
}

// ---------------------------------------------------------------------------
// L1: fused launch — two independent block families:
//   [0, nch):        bucketed counting-sort of edge chunks
//   [nch, +RELU_B):  relu(h)->out, zero h2, fp16 copy of h (only launch A)
// ---------------------------------------------------------------------------
__global__ void sort_relu_kernel(const int* __restrict__ src,
                                 const int* __restrict__ dst,
                                 const int* __restrict__ rel,
                                 const float4* __restrict__ h,
                                 float4* __restrict__ out,
                                 int chunk_base, int nch) {
    const int tid = threadIdx.x;
    if (blockIdx.x >= nch) {
        // ---- relu + fp16-split + h2-zero family ----
        int i = (blockIdx.x - nch) * 256 + tid;
        const int n4 = N_NODES * 64 / 4;
        if (i >= n4) return;
        float4 v = h[i];
        unsigned p0 = pk2h(__float2half_rn(v.x), __float2half_rn(v.y));
        unsigned p1 = pk2h(__float2half_rn(v.z), __float2half_rn(v.w));
        ((uint2*)d_hf)[i] = make_uint2(p0, p1);
        v.x = fmaxf(v.x, 0.f);
        v.y = fmaxf(v.y, 0.f);
        v.z = fmaxf(v.z, 0.f);
        v.w = fmaxf(v.w, 0.f);
        out[i] = v;
        out[n4 + i] = make_float4(0.f, 0.f, 0.f, 0.f);
        return;
    }
    // ---- bucketed sort family ----
    __shared__ int hc[N_REL];
    __shared__ int rl[CHUNK];
    if (tid < N_REL) hc[tid] = 0;
    __syncthreads();
    int base = (chunk_base + blockIdx.x) * CHUNK;
#pragma unroll 4
    for (int j = tid; j < CHUNK; j += 256) {
        int e = base + j;
        int rv = (e < E_EDGES) ? __ldg(&rel[e]) : -1;
        rl[j] = rv;
        if (rv >= 0) atomicAdd(&hc[rv], 1);
    }
    __syncthreads();
    if (tid < N_REL) hc[tid] = atomicAdd(&d_cur[tid], hc[tid]);
    __syncthreads();
#pragma unroll 2
    for (int j = tid; j < CHUNK; j += 256) {
        int rv = rl[j];
        if (rv >= 0) {
            int e = base + j;
            int p = atomicAdd(&hc[rv], 1);
            d_se[rv * BUCKET + p] = make_int2(src[e], dst[e]);
        }
    }
}

// ---------------------------------------------------------------------------
// L3: fp16 2-product HMMA tile GEMM + scatter (R15-proven, verbatim except
//     constant bucket base + d_cur count).
//   D = A_f16 * W_hi + A_f16 * W_lo; double-buffered cp.async (single A
//   array); B frags hoisted to registers; dedicated D staging (288 B stride);
//   row-coalesced red.global.add.v4 scatter. 2 syncs/tile.
// ---------------------------------------------------------------------------
__global__ void __launch_bounds__(256, 2)
mma_scatter_kernel(float* __restrict__ h2) {
    extern __shared__ __align__(16) char dsm[];
    const unsigned sb = smem_u32(dsm);

    const int r = blockIdx.y;
    const int c = blockIdx.x;
    const int start = r * BUCKET;
    const int cnt   = d_cur[r];
    const int seg   = (cnt + NC - 1) / NC;
    const int s0    = start + c * seg;
    const int s1    = min(start + cnt, s0 + seg);

    const int tid  = threadIdx.x;
    const int wid  = tid >> 5;
    const int lane = tid & 31;
    const int g    = lane >> 2;      // fragment row group
    const int t    = lane & 3;       // fragment col group

    // ---- stage B = W[r] as [n][k] fp16 hi/lo, padded rows ----
    for (int idx = tid; idx < 2048; idx += 256) {
        int k2 = idx >> 6;
        int o  = idx & 63;
        float x0 = d_W[r * 4096 + (2 * k2) * 64 + o];
        float x1 = d_W[r * 4096 + (2 * k2 + 1) * 64 + o];
        __half h0 = __float2half_rn(x0), h1 = __float2half_rn(x1);
        __half l0 = __float2half_rn(x0 - __half2float(h0));
        __half l1 = __float2half_rn(x1 - __half2float(h1));
        *(unsigned*)(dsm + SM_BHI + o * A_STRIDE + k2 * 4) = pk2h(h0, h1);
        *(unsigned*)(dsm + SM_BLO + o * A_STRIDE + k2 * 4) = pk2h(l0, l1);
    }
    __syncthreads();

    const int rowblk = (wid & 3) * 32;   // this warp's 32 edge-rows (MMA)
    const int nhalf  = wid >> 2;         // this warp's 32-col half
    const unsigned a_lane_off =
        (unsigned)((lane & 15) * A_STRIDE + ((lane >> 4) & 1) * 16);
    const unsigned b4_lane_off =
        (unsigned)(((lane >> 4) & 1) * 8 * A_STRIDE + (lane & 7) * A_STRIDE
                   + ((lane >> 3) & 1) * 16);

    // ---- hoist ALL B fragments into registers (CTA-constant W) ----
    unsigned bh[4][2][4], bl[4][2][4];
#pragma unroll
    for (int kb = 0; kb < 4; kb++)
#pragma unroll
        for (int p = 0; p < 2; p++) {
            unsigned baddr = sb
                + (unsigned)((nhalf * 32 + p * 16) * A_STRIDE + kb * 32)
                + b4_lane_off;
            ldsm_x4(bh[kb][p], baddr + SM_BHI);
            ldsm_x4(bl[kb][p], baddr + SM_BLO);
        }

    if (s0 >= s1) return;

    const int gseg   = tid & 7;          // 16 B segment within a 128 B row
    const int grow_b = tid >> 3;         // row base (0..31), +32 per pass

    const int nt = (s1 - s0 + TILE_M - 1) / TILE_M;

    int2 sd_pf[4];
#pragma unroll
    for (int p = 0; p < 4; p++) {
        int eidx = min(s0 + p * 32 + grow_b, s1 - 1);
        sd_pf[p] = __ldg(&d_se[eidx]);
    }

    auto issue_gather = [&](const int2 sd[4], int buf) {
        const unsigned abase = sb + (unsigned)(buf * ABUF_SZ);
#pragma unroll
        for (int p = 0; p < 4; p++) {
            int grow = p * 32 + grow_b;
            if (gseg == 0)
                *(int*)(dsm + SM_DST + buf * 512 + grow * 4) = sd[p].y;
            unsigned da = abase + (unsigned)(grow * A_STRIDE + gseg * 16);
            const uint4* gh = d_hf + (long)sd[p].x * 8 + gseg;
            asm volatile("cp.async.ca.shared.global [%0], [%1], 16;"
                         :: "r"(da), "l"(gh) : "memory");
        }
        asm volatile("cp.async.commit_group;" ::: "memory");
    };

    issue_gather(sd_pf, 0);
#pragma unroll
    for (int p = 0; p < 4; p++) {
        int eidx = min(s0 + TILE_M + p * 32 + grow_b, s1 - 1);
        sd_pf[p] = __ldg(&d_se[eidx]);
    }

    for (int it = 0; it < nt; it++) {
        const int tb  = s0 + it * TILE_M;
        const int mt  = min(TILE_M, s1 - tb);
        const int cur = it & 1;

        asm volatile("cp.async.wait_group 0;" ::: "memory");
        __syncthreads();   // A ready; also separates prev scatter from D write

        if (it + 1 < nt) issue_gather(sd_pf, cur ^ 1);
#pragma unroll
        for (int p = 0; p < 4; p++) {
            int eidx = min(tb + 2 * TILE_M + p * 32 + grow_b, s1 - 1);
            sd_pf[p] = __ldg(&d_se[eidx]);
        }

        // ---- MMA on buffer `cur` (B already in registers) ----
        const unsigned abuf = sb + (unsigned)(cur * ABUF_SZ);
        float cf[2][4][4];
#pragma unroll
        for (int m = 0; m < 2; m++)
#pragma unroll
            for (int nb = 0; nb < 4; nb++)
#pragma unroll
                for (int q = 0; q < 4; q++) cf[m][nb][q] = 0.f;

#pragma unroll
        for (int kb = 0; kb < 4; kb++) {
#pragma unroll
            for (int m = 0; m < 2; m++) {
                unsigned ah[4];
                unsigned aaddr = abuf
                    + (unsigned)((rowblk + m * 16) * A_STRIDE + kb * 32)
                    + a_lane_off;
                ldsm_x4(ah, aaddr);
#pragma unroll
                for (int nb = 0; nb < 4; nb++) {
                    unsigned b0h = bh[kb][nb >> 1][(nb & 1) * 2];
                    unsigned b1h = bh[kb][nb >> 1][(nb & 1) * 2 + 1];
                    unsigned b0l = bl[kb][nb >> 1][(nb & 1) * 2];
                    unsigned b1l = bl[kb][nb >> 1][(nb & 1) * 2 + 1];
                    mma_f16(cf[m][nb], ah, b0h, b1h);
                    mma_f16(cf[m][nb], ah, b0l, b1l);
                }
            }
        }

        // ---- stage D into dedicated region (288 B rows, proven banking) ----
#pragma unroll
        for (int m = 0; m < 2; m++) {
            int row0 = rowblk + m * 16 + g;
#pragma unroll
            for (int nb = 0; nb < 4; nb++) {
                int col = nhalf * 32 + nb * 8 + 2 * t;
                *(float2*)(dsm + SM_D + row0 * D_STRIDE + col * 4) =
                    make_float2(cf[m][nb][0], cf[m][nb][1]);
                *(float2*)(dsm + SM_D + (row0 + 8) * D_STRIDE + col * 4) =
                    make_float2(cf[m][nb][2], cf[m][nb][3]);
            }
        }
        __syncthreads();

        // ---- row-coalesced scatter: 2 rows per warp-instr ----
        {
            const int seg16 = lane & 15;
            const int rhalf = lane >> 4;
#pragma unroll
            for (int i = 0; i < 8; i++) {
                int row = wid * 16 + 2 * i + rhalf;
                int dn  = *(const int*)(dsm + SM_DST + cur * 512 + row * 4);
                float4 v = *(const float4*)(dsm + SM_D
                                            + row * D_STRIDE + seg16 * 16);
                if (row < mt) {
                    float* p = h2 + (long)dn * 64 + seg16 * 4;
                    asm volatile("red.global.add.v4.f32 [%0], {%1,%2,%3,%4};"
                                 :: "l"(p), "f"(v.x), "f"(v.y), "f"(v.z), "f"(v.w)
                                 : "memory");
                }
            }
        }
        // top-of-loop wait+sync separates this scatter from next D write
    }
}

// ---------------------------------------------------------------------------
extern "C" void kernel_launch(void* const* d_in, const int* in_sizes, int n_in,
                              void* d_out, int out_size) {
    const float* h      = (const float*)d_in[0];
    const float* weight = (const float*)d_in[1];
    const float* w_comp = (const float*)d_in[2];
    const int*   src    = (const int*)d_in[3];
    const int*   dst    = (const int*)d_in[4];
    const int*   rel    = (const int*)d_in[5];
    float* out = (float*)d_out;          // [h_new (N*64) | h2 (N*64)]
    float* h2  = out + N_NODES * 64;

    static int smem_set = 0;
    if (!smem_set) {
        cudaFuncSetAttribute(mma_scatter_kernel,
                             cudaFuncAttributeMaxDynamicSharedMemorySize, SM_BYTES);
        smem_set = 1;
    }

    // Launch 0: W basis combination + d_cur reset
    l0_kernel<<<257, 256>>>(weight, w_comp);
    // Launch 1: sort chunks [0,NCH_A) + relu/fp16/zero family (fused overlap)
    sort_relu_kernel<<<NCH_A + RELU_B, 256>>>(src, dst, rel,
                                              (const float4*)h, (float4*)out,
                                              0, NCH_A);
    // Launch 2: sort chunks [NCH_A, NCHUNKS)
    sort_relu_kernel<<<NCHUNKS - NCH_A, 256>>>(src, dst, rel,
                                               (const float4*)h, (float4*)out,
                                               NCH_A, NCHUNKS);
    // Launch 3: fp16 HMMA edge GEMM + scatter (capture slot 3)
    dim3 grid(NC, N_REL);
    mma_scatter_kernel<<<grid, 256, SM_BYTES>>>(h2);
}